// round 14
// baseline (speedup 1.0000x reference)
#include <cuda_runtime.h>

#define H      4096
#define TMAX   16384
#define EXP    8
#define FULLM  0xFFFFFFFFu
#define STAGES 8
#define ROWB   16384            // bytes per row stage (full 4096-float row)

// Phase-1 partials: [row][16 warps][8 slots] = 8 MB
// slot j holds expert perm[j] = 2*(j&3) + (j>>2)  -> {0,2,4,6,1,3,5,7}
__device__ float g_scratch[(size_t)TMAX * 16 * EXP];

typedef unsigned long long u64;

__device__ __forceinline__ u64 fma2(u64 a, u64 b, u64 c) {
    u64 d; asm("fma.rn.f32x2 %0,%1,%2,%3;" : "=l"(d) : "l"(a), "l"(b), "l"(c)); return d;
}
__device__ __forceinline__ u64 mul2(u64 a, u64 b) {
    u64 d; asm("mul.rn.f32x2 %0,%1,%2;" : "=l"(d) : "l"(a), "l"(b)); return d;
}
__device__ __forceinline__ float hadd2(u64 v) {
    float lo = __uint_as_float((unsigned)v);
    float hi = __uint_as_float((unsigned)(v >> 32));
    return lo + hi;
}
__device__ __forceinline__ void lds128(u64& a, u64& b, unsigned addr) {
    asm volatile("ld.shared.v2.u64 {%0,%1},[%2];" : "=l"(a), "=l"(b) : "r"(addr));
}
__device__ __forceinline__ void cp16(unsigned saddr, const void* gaddr) {
    asm volatile("cp.async.cg.shared.global [%0], [%1], 16;" :: "r"(saddr), "l"(gaddr));
}
__device__ __forceinline__ void cp_commit() {
    asm volatile("cp.async.commit_group;" ::: "memory");
}
__device__ __forceinline__ void cp_waitN() {
    asm volatile("cp.async.wait_group %0;" :: "n"(STAGES - 1) : "memory");
}

// ── Phase 1: streaming GEMV partials.
//   512 threads (16 warps). Warp w owns 256 consecutive floats of each row.
//   Lane = (group g=lane>>2 of 32 floats, expert-pair p=lane&3 -> {2p,2p+1}).
//   x staged via cp.async (lanes copy pieces, consumers read warp-wide after
//   wait+syncwarp). 8 LDS.128 broadcast reads (bank-rotated, conflict-free),
//   32 fma2, and only THREE shuffles to finish the reduction.
__global__ void __launch_bounds__(512, 1)
router_p1(const float* __restrict__ x, const float* __restrict__ W, int T) {
    extern __shared__ char smem[];   // STAGES * 16KB = 128KB

    const int tid  = threadIdx.x;
    const int lane = tid & 31;
    const int warp = tid >> 5;
    const int g    = lane >> 2;     // data group (0..7): 32 floats
    const int p    = lane & 3;      // expert pair: experts 2p, 2p+1
    const int nb   = gridDim.x;

    // W regs: 2 experts x 32 k, loaded in the rotated piece order the
    // consumer uses: piece j reads x sub-piece ((j+g)&7).
    const int e0 = 2 * p;
    u64 wa[8][2], wb[8][2];         // [j][lo/hi] for experts e0, e0+1
#pragma unroll
    for (int j = 0; j < 8; j++) {
        int koff = warp * 256 + g * 32 + (((j + g) & 7) * 4);
        ulonglong2 t0 = *reinterpret_cast<const ulonglong2*>(W + e0 * H + koff);
        ulonglong2 t1 = *reinterpret_cast<const ulonglong2*>(W + (e0 + 1) * H + koff);
        wa[j][0] = t0.x; wa[j][1] = t0.y;
        wb[j][0] = t1.x; wb[j][1] = t1.y;
    }

    unsigned sbase;
    asm("{ .reg .u64 t; cvta.to.shared.u64 t, %1; cvt.u32.u64 %0, t; }"
        : "=r"(sbase) : "l"(smem));
    // copy destinations: pieces lane and lane+32 of warp's 64 16B pieces
    const unsigned dstA = sbase + warp * 1024 + lane * 16;
    const unsigned dstB = dstA + 512;
    // read base: group g's 128B sub-chunk
    const unsigned ldB0 = sbase + warp * 1024 + g * 128;

    const char* xg = reinterpret_cast<const char*>(x);
    const size_t offA = (size_t)warp * 1024 + lane * 16;
    const size_t offB = offA + 512;

    const int r0 = blockIdx.x;

    // prologue: fill STAGES groups
#pragma unroll
    for (int s = 0; s < STAGES; s++) {
        int r = r0 + s * nb;
        if (r < T) {
            cp16(dstA + s * ROWB, xg + (size_t)r * ROWB + offA);
            cp16(dstB + s * ROWB, xg + (size_t)r * ROWB + offB);
        }
        cp_commit();
    }

    int s = 0;
    for (int r = r0; r < T; r += nb) {
        cp_waitN();
        __syncwarp();   // REQUIRED: lanes read pieces copied by other lanes

        const unsigned B = ldB0 + s * ROWB;
        u64 acc0, acc1;
        {
            u64 xlo, xhi;
            lds128(xlo, xhi, B + (g & 7) * 16);           // j=0 -> piece (0+g)&7
            acc0 = mul2(xlo, wa[0][0]);
            acc0 = fma2(xhi, wa[0][1], acc0);
            acc1 = mul2(xlo, wb[0][0]);
            acc1 = fma2(xhi, wb[0][1], acc1);
        }
#pragma unroll
        for (int j = 1; j < 8; j++) {
            u64 xlo, xhi;
            lds128(xlo, xhi, B + (((j + g) & 7) * 16));
            acc0 = fma2(xlo, wa[j][0], acc0);
            acc0 = fma2(xhi, wa[j][1], acc0);
            acc1 = fma2(xlo, wb[j][0], acc1);
            acc1 = fma2(xhi, wb[j][1], acc1);
        }
        float A0 = hadd2(acc0);     // expert 2p over group g
        float A1 = hadd2(acc1);     // expert 2p+1 over group g

        // 3-shfl reduction over the 8 groups:
        // mask4 splits the pair (bit2 chooses expert), masks 8,16 sum groups.
        {
            bool hi = (lane & 4) != 0;
            float send = hi ? A0 : A1;
            float recv = __shfl_xor_sync(FULLM, send, 4);
            float v = (hi ? A1 : A0) + recv;
            v += __shfl_xor_sync(FULLM, v, 8);
            v += __shfl_xor_sync(FULLM, v, 16);
            // lane holds expert 2*(lane&3) + ((lane>>2)&1), replicated x4
            if (lane < 8)
                g_scratch[((size_t)r * 16 + warp) * EXP + lane] = v;
        }

        int rp = r + STAGES * nb;
        if (rp < T) {
            cp16(dstA + s * ROWB, xg + (size_t)rp * ROWB + offA);
            cp16(dstB + s * ROWB, xg + (size_t)rp * ROWB + offB);
        }
        cp_commit();

        s = (s == STAGES - 1) ? 0 : s + 1;
    }
}

// ── Phase 2: FOUR rows per warp (octet decomposition).
//   Scratch slots are expert-permuted: slot j = expert 2*(j&3)+(j>>2).
//   inv[e] gives the slot of true expert e.
__global__ void __launch_bounds__(256)
router_p2(int T, float* __restrict__ out, int flags) {
    const int lane  = threadIdx.x & 31;
    const int warpG = (blockIdx.x * 256 + threadIdx.x) >> 5;
    const int oct   = lane >> 3;   // which of 4 rows
    const int ol    = lane & 7;    // slot index within row
    const int r     = warpG * 4 + oct;
    if (warpG * 4 >= T) return;    // T % 4 == 0

    const float4* ptr0 = reinterpret_cast<const float4*>(g_scratch + ((size_t)r * 16 + ol) * EXP);
    const float4* ptr1 = reinterpret_cast<const float4*>(g_scratch + ((size_t)r * 16 + ol + 8) * EXP);
    float4 u0 = ptr0[0], v0 = ptr0[1], u1 = ptr1[0], v1q = ptr1[1];
    float a[EXP] = {u0.x + u1.x, u0.y + u1.y, u0.z + u1.z, u0.w + u1.w,
                    v0.x + v1q.x, v0.y + v1q.y, v0.z + v1q.z, v0.w + v1q.w};

    // octet butterfly masks {4,2,1}: octet lane l ends with slot-component l
    {
        bool hi = (lane & 4) != 0;
        float s0 = hi ? a[0] : a[4];
        float s1 = hi ? a[1] : a[5];
        float s2 = hi ? a[2] : a[6];
        float s3 = hi ? a[3] : a[7];
        s0 = __shfl_xor_sync(FULLM, s0, 4);
        s1 = __shfl_xor_sync(FULLM, s1, 4);
        s2 = __shfl_xor_sync(FULLM, s2, 4);
        s3 = __shfl_xor_sync(FULLM, s3, 4);
        a[0] = (hi ? a[4] : a[0]) + s0;
        a[1] = (hi ? a[5] : a[1]) + s1;
        a[2] = (hi ? a[6] : a[2]) + s2;
        a[3] = (hi ? a[7] : a[3]) + s3;
    }
    {
        bool hi = (lane & 2) != 0;
        float s0 = hi ? a[0] : a[2];
        float s1 = hi ? a[1] : a[3];
        s0 = __shfl_xor_sync(FULLM, s0, 2);
        s1 = __shfl_xor_sync(FULLM, s1, 2);
        a[0] = (hi ? a[2] : a[0]) + s0;
        a[1] = (hi ? a[3] : a[1]) + s1;
    }
    {
        bool hi = (lane & 1) != 0;
        float s0 = hi ? a[0] : a[1];
        s0 = __shfl_xor_sync(FULLM, s0, 1);
        a[0] = (hi ? a[1] : a[0]) + s0;
    }
    float t = a[0];   // logit of expert perm[ol]

    // softmax within octet (set-wise: labeling irrelevant)
    float m = t;
    m = fmaxf(m, __shfl_xor_sync(FULLM, m, 4));
    m = fmaxf(m, __shfl_xor_sync(FULLM, m, 2));
    m = fmaxf(m, __shfl_xor_sync(FULLM, m, 1));
    float pz = __expf(t - m);
    float sden = pz;
    sden += __shfl_xor_sync(FULLM, sden, 4);
    sden += __shfl_xor_sync(FULLM, sden, 2);
    sden += __shfl_xor_sync(FULLM, sden, 1);
    float sc = __fdividef(pz, sden);   // score of expert perm[ol]

    // broadcast all 8 slot-scores within the octet
    float se[EXP];
#pragma unroll
    for (int j = 0; j < EXP; j++)
        se[j] = __shfl_sync(FULLM, sc, (lane & 24) | j);

    // inv[e] = slot holding true expert e
    const int inv[EXP] = {0, 4, 1, 5, 2, 6, 3, 7};

    // scores in TRUE expert order: two STG.128 per row
    if (ol < 2) {
        float4 o = ol ? make_float4(se[inv[4]], se[inv[5]], se[inv[6]], se[inv[7]])
                      : make_float4(se[inv[0]], se[inv[1]], se[inv[2]], se[inv[3]]);
        reinterpret_cast<float4*>(out + (size_t)r * EXP)[ol] = o;
    }

    // flat top-2 over TRUE expert order (ties -> lower true index)
    float w1 = se[inv[0]]; int i1 = 0;
#pragma unroll
    for (int e = 1; e < EXP; e++)
        if (se[inv[e]] > w1) { w1 = se[inv[e]]; i1 = e; }
    float w2 = -1.0f; int i2 = 0;
#pragma unroll
    for (int e = 0; e < EXP; e++)
        if (e != i1 && se[inv[e]] > w2) { w2 = se[inv[e]]; i2 = e; }

    if (ol == 2 && (flags & 1)) {
        float* outW = out + (size_t)T * EXP;
        outW[(size_t)r * 2 + 0] = w1;
        outW[(size_t)r * 2 + 1] = w2;
    }
    if (ol == 3 && (flags & 2)) {
        float* outI = out + (size_t)T * (EXP + 2);
        outI[(size_t)r * 2 + 0] = (float)i1;
        outI[(size_t)r * 2 + 1] = (float)i2;
    }
}

extern "C" void kernel_launch(void* const* d_in, const int* in_sizes, int n_in,
                              void* d_out, int out_size) {
    const float* x = (const float*)d_in[0];
    const float* W = (const float*)d_in[1];

    int T = in_sizes[0] / H;  // 16384

    int dev = 0;
    cudaGetDevice(&dev);
    int sm = 148;
    cudaDeviceGetAttribute(&sm, cudaDevAttrMultiProcessorCount, dev);

    int flags = 0;
    if (out_size >= T * (EXP + 2)) flags |= 1;
    if (out_size >= T * (EXP + 4)) flags |= 2;

    static int smemSet = 0;
    if (!smemSet) {
        cudaFuncSetAttribute(router_p1, cudaFuncAttributeMaxDynamicSharedMemorySize,
                             STAGES * ROWB);
        smemSet = 1;
    }

    router_p1<<<sm, 512, STAGES * ROWB>>>(x, W, T);
    int blocks2 = ((T / 4) * 32 + 255) / 256;   // 4 rows per warp
    router_p2<<<blocks2, 256>>>(T, (float*)d_out, flags);
}

// round 15
// speedup vs baseline: 1.0936x; 1.0936x over previous
#include <cuda_runtime.h>

#define H      4096
#define TMAX   16384
#define EXP    8
#define FULLM  0xFFFFFFFFu
#define STAGES 8
#define ROWB   16384            // bytes per full row
#define HROWB  8192             // bytes per half row (one block's share)

// fp32 logits accumulated by atomics: [row][expert] = 512 KB
__device__ float g_logits[(size_t)TMAX * EXP];

typedef unsigned long long u64;

__device__ __forceinline__ u64 fma2(u64 a, u64 b, u64 c) {
    u64 d; asm("fma.rn.f32x2 %0,%1,%2,%3;" : "=l"(d) : "l"(a), "l"(b), "l"(c)); return d;
}
__device__ __forceinline__ u64 mul2(u64 a, u64 b) {
    u64 d; asm("mul.rn.f32x2 %0,%1,%2;" : "=l"(d) : "l"(a), "l"(b)); return d;
}
__device__ __forceinline__ float hadd2(u64 v) {
    float lo = __uint_as_float((unsigned)v);
    float hi = __uint_as_float((unsigned)(v >> 32));
    return lo + hi;
}
__device__ __forceinline__ void lds128(u64& a, u64& b, unsigned addr) {
    asm volatile("ld.shared.v2.u64 {%0,%1},[%2];" : "=l"(a), "=l"(b) : "r"(addr));
}
__device__ __forceinline__ void cp16(unsigned saddr, const void* gaddr) {
    asm volatile("cp.async.cg.shared.global [%0], [%1], 16;" :: "r"(saddr), "l"(gaddr));
}
__device__ __forceinline__ void cp_commit() {
    asm volatile("cp.async.commit_group;" ::: "memory");
}
__device__ __forceinline__ void cp_waitN() {
    asm volatile("cp.async.wait_group %0;" :: "n"(STAGES - 1) : "memory");
}

// Reduce 8 per-lane values across 32 lanes (vector-halving butterfly, 9 shfls).
// Result: lane 4e holds the sum for expert e.
__device__ __forceinline__ float reduce8(float a[8]) {
    const int lane = threadIdx.x & 31;
    {
        bool hi = (lane & 16) != 0;
        float s0 = hi ? a[0] : a[4];
        float s1 = hi ? a[1] : a[5];
        float s2 = hi ? a[2] : a[6];
        float s3 = hi ? a[3] : a[7];
        s0 = __shfl_xor_sync(FULLM, s0, 16);
        s1 = __shfl_xor_sync(FULLM, s1, 16);
        s2 = __shfl_xor_sync(FULLM, s2, 16);
        s3 = __shfl_xor_sync(FULLM, s3, 16);
        a[0] = (hi ? a[4] : a[0]) + s0;
        a[1] = (hi ? a[5] : a[1]) + s1;
        a[2] = (hi ? a[6] : a[2]) + s2;
        a[3] = (hi ? a[7] : a[3]) + s3;
    }
    {
        bool hi = (lane & 8) != 0;
        float s0 = hi ? a[0] : a[2];
        float s1 = hi ? a[1] : a[3];
        s0 = __shfl_xor_sync(FULLM, s0, 8);
        s1 = __shfl_xor_sync(FULLM, s1, 8);
        a[0] = (hi ? a[2] : a[0]) + s0;
        a[1] = (hi ? a[3] : a[1]) + s1;
    }
    {
        bool hi = (lane & 4) != 0;
        float s0 = hi ? a[0] : a[1];
        s0 = __shfl_xor_sync(FULLM, s0, 4);
        a[0] = (hi ? a[1] : a[0]) + s0;
    }
    float v = a[0];
    v += __shfl_xor_sync(FULLM, v, 2);
    v += __shfl_xor_sync(FULLM, v, 1);
    return v;
}

// ── Phase 1: streaming GEMV partials, 2 blocks per SM.
//   Grid = 2*SMs; block (rb, half) owns half-row columns [half*2048, +2048).
//   256 threads; thread owns 8 k (float4 at half*2048+4t and half*2048+1024+4t).
//   8-deep per-thread cp.async pipeline (private slots, no block sync).
//   Warp partial -> one fp32 atomicAdd per expert into g_logits.
__global__ void __launch_bounds__(256, 2)
router_p1(const float* __restrict__ x, const float* __restrict__ W, int T) {
    extern __shared__ char smem[];   // STAGES * 8KB = 64KB

    const int tid  = threadIdx.x;
    const int lane = tid & 31;
    const int half = blockIdx.x & 1;
    const int nb   = gridDim.x >> 1;
    const int r0   = blockIdx.x >> 1;

    const int colF = half * 2048;    // this block's first column (floats)

    // W regs: 8 experts x 2 chunks x 16B = 64 regs
    u64 wa0[EXP], wa1[EXP], wb0[EXP], wb1[EXP];
#pragma unroll
    for (int e = 0; e < EXP; e++) {
        ulonglong2 ta = *reinterpret_cast<const ulonglong2*>(W + e * H + colF + tid * 4);
        ulonglong2 tb = *reinterpret_cast<const ulonglong2*>(W + e * H + colF + 1024 + tid * 4);
        wa0[e] = ta.x; wa1[e] = ta.y;
        wb0[e] = tb.x; wb1[e] = tb.y;
    }

    unsigned sbase;
    asm("{ .reg .u64 t; cvta.to.shared.u64 t, %1; cvt.u32.u64 %0, t; }"
        : "=r"(sbase) : "l"(smem));
    const unsigned myA = sbase + tid * 16;   // chunk A slot (bytes [0,4K) of stage)
    const unsigned myB = myA + 4096;         // chunk B slot (bytes [4K,8K))

    const char* xg = reinterpret_cast<const char*>(x);
    const size_t offA = (size_t)half * HROWB + tid * 16;
    const size_t offB = offA + 4096;

    // prologue: fill STAGES groups
#pragma unroll
    for (int s = 0; s < STAGES; s++) {
        int r = r0 + s * nb;
        if (r < T) {
            cp16(myA + s * HROWB, xg + (size_t)r * ROWB + offA);
            cp16(myB + s * HROWB, xg + (size_t)r * ROWB + offB);
        }
        cp_commit();
    }

    int s = 0;
    for (int r = r0; r < T; r += nb) {
        cp_waitN();
        __syncwarp();

        u64 ax0, ax1, bx0, bx1;
        lds128(ax0, ax1, myA + s * HROWB);
        lds128(bx0, bx1, myB + s * HROWB);

        float a8[EXP];
#pragma unroll
        for (int e = 0; e < EXP; e++) {
            u64 acc = mul2(ax0, wa0[e]);
            acc = fma2(ax1, wa1[e], acc);
            acc = fma2(bx0, wb0[e], acc);
            acc = fma2(bx1, wb1[e], acc);
            a8[e] = hadd2(acc);
        }

        float v = reduce8(a8);
        if ((lane & 3) == 0)
            atomicAdd(g_logits + (size_t)r * EXP + (lane >> 2), v);

        int rp = r + STAGES * nb;
        if (rp < T) {
            cp16(myA + s * HROWB, xg + (size_t)rp * ROWB + offA);
            cp16(myB + s * HROWB, xg + (size_t)rp * ROWB + offB);
        }
        cp_commit();

        s = (s == STAGES - 1) ? 0 : s + 1;
    }
}

// ── Phase 2: FOUR rows per warp (octet decomposition) on finished logits.
//   Lane's load is g_logits[warpG*32 + lane] — one coalesced LDG.32.
__global__ void __launch_bounds__(256)
router_p2(int T, float* __restrict__ out, int flags) {
    const int lane  = threadIdx.x & 31;
    const int warpG = (blockIdx.x * 256 + threadIdx.x) >> 5;
    const int oct   = lane >> 3;   // which of 4 rows
    const int ol    = lane & 7;    // expert index
    const int r     = warpG * 4 + oct;
    if (warpG * 4 >= T) return;    // T % 4 == 0

    float t = g_logits[(size_t)warpG * 32 + lane];   // logit[expert ol] of row r

    // softmax within octet (masks {4,2,1})
    float m = t;
    m = fmaxf(m, __shfl_xor_sync(FULLM, m, 4));
    m = fmaxf(m, __shfl_xor_sync(FULLM, m, 2));
    m = fmaxf(m, __shfl_xor_sync(FULLM, m, 1));
    float pz = __expf(t - m);
    float sden = pz;
    sden += __shfl_xor_sync(FULLM, sden, 4);
    sden += __shfl_xor_sync(FULLM, sden, 2);
    sden += __shfl_xor_sync(FULLM, sden, 1);
    float sc = __fdividef(pz, sden);

    // broadcast all 8 scores within the octet (true expert order)
    float se[EXP];
#pragma unroll
    for (int j = 0; j < EXP; j++)
        se[j] = __shfl_sync(FULLM, sc, (lane & 24) | j);

    // scores: two STG.128 per row (octet lanes 0 and 1)
    if (ol < 2) {
        float4 o = ol ? make_float4(se[4], se[5], se[6], se[7])
                      : make_float4(se[0], se[1], se[2], se[3]);
        reinterpret_cast<float4*>(out + (size_t)r * EXP)[ol] = o;
    }

    // flat top-2 (ties -> lower index, matching lax.top_k)
    float w1 = se[0]; int i1 = 0;
#pragma unroll
    for (int j = 1; j < EXP; j++)
        if (se[j] > w1) { w1 = se[j]; i1 = j; }
    float w2 = -1.0f; int i2 = 0;
#pragma unroll
    for (int j = 0; j < EXP; j++)
        if (j != i1 && se[j] > w2) { w2 = se[j]; i2 = j; }

    if (ol == 2 && (flags & 1)) {
        float* outW = out + (size_t)T * EXP;
        outW[(size_t)r * 2 + 0] = w1;
        outW[(size_t)r * 2 + 1] = w2;
    }
    if (ol == 3 && (flags & 2)) {
        float* outI = out + (size_t)T * (EXP + 2);
        outI[(size_t)r * 2 + 0] = (float)i1;
        outI[(size_t)r * 2 + 1] = (float)i2;
    }
}

extern "C" void kernel_launch(void* const* d_in, const int* in_sizes, int n_in,
                              void* d_out, int out_size) {
    const float* x = (const float*)d_in[0];
    const float* W = (const float*)d_in[1];

    int T = in_sizes[0] / H;  // 16384

    int dev = 0;
    cudaGetDevice(&dev);
    int sm = 148;
    cudaDeviceGetAttribute(&sm, cudaDevAttrMultiProcessorCount, dev);

    int flags = 0;
    if (out_size >= T * (EXP + 2)) flags |= 1;
    if (out_size >= T * (EXP + 4)) flags |= 2;

    static void* logitsAddr = nullptr;
    static int smemSet = 0;
    if (!smemSet) {
        cudaFuncSetAttribute(router_p1, cudaFuncAttributeMaxDynamicSharedMemorySize,
                             STAGES * HROWB);
        cudaGetSymbolAddress(&logitsAddr, g_logits);
        smemSet = 1;
    }

    // zero the atomic accumulation buffer (graph-capturable async memset)
    cudaMemsetAsync(logitsAddr, 0, (size_t)T * EXP * sizeof(float), 0);

    router_p1<<<2 * sm, 256, STAGES * HROWB>>>(x, W, T);
    int blocks2 = ((T / 4) * 32 + 255) / 256;   // 4 rows per warp
    router_p2<<<blocks2, 256>>>(T, (float*)d_out, flags);
}